// round 3
// baseline (speedup 1.0000x reference)
#include <cuda_runtime.h>
#include <cstdint>

#define STATE_DIM 1024
#define NACT 256
#define BM 256
#define BN 128
#define BK 32
#define PADK 36                      // floats per smem row (144B: 16B-aligned, conflict-free)
#define NSTEPS (STATE_DIM / BK)      // 32
#define THREADS 512

#define A_STG_FLOATS (BM * PADK)     // 9216
#define B_STG_FLOATS (BN * PADK)     // 4608
#define SMEM_FLOATS (2 * (A_STG_FLOATS + B_STG_FLOATS))
#define SMEM_BYTES (SMEM_FLOATS * 4) // 110592

__device__ float g_weff[NACT * STATE_DIM];   // 1 MB static scratch (allowed)

// ---------------- helpers ----------------
__device__ __forceinline__ uint32_t smem_u32(const void* p) {
    uint32_t a;
    asm("{ .reg .u64 t; cvta.to.shared.u64 t, %1; cvt.u32.u64 %0, t; }" : "=r"(a) : "l"(p));
    return a;
}
__device__ __forceinline__ void cp16(uint32_t dst, const void* src) {
    asm volatile("cp.async.cg.shared.global [%0], [%1], 16;" :: "r"(dst), "l"(src) : "memory");
}
__device__ __forceinline__ uint32_t f2tf32(float v) {
    uint32_t r;
    asm("cvt.rna.tf32.f32 %0, %1;" : "=r"(r) : "f"(v));
    return r;
}
__device__ __forceinline__ float tf32r(float v) {   // round fp32 -> nearest tf32 value
    return __uint_as_float(f2tf32(v));
}
__device__ __forceinline__ void mma_tf32(float* c, const uint32_t* a, const uint32_t* b) {
    asm volatile(
        "mma.sync.aligned.m16n8k8.row.col.f32.tf32.tf32.f32 "
        "{%0,%1,%2,%3}, {%4,%5,%6,%7}, {%8,%9}, {%0,%1,%2,%3};"
        : "+f"(c[0]), "+f"(c[1]), "+f"(c[2]), "+f"(c[3])
        : "r"(a[0]), "r"(a[1]), "r"(a[2]), "r"(a[3]), "r"(b[0]), "r"(b[1]));
}

// ---------------- W_eff precompute ----------------
// Hamilton product is linear in x: h = M_n x_n with M_n from q=tanh(g).
// W_eff[a, 4n+d] = sum_c W[a,4n+c] * M_n[c,d], rounded to tf32 (rna).
__global__ void weff_kernel(const float* __restrict__ W, const float* __restrict__ g) {
    const int a = blockIdx.x;
    const int n = threadIdx.x;
    float4 q4 = ((const float4*)g)[n];
    float qw = tanhf(q4.x), qi = tanhf(q4.y), qj = tanhf(q4.z), qk = tanhf(q4.w);
    float4 w4 = ((const float4*)(W + (size_t)a * STATE_DIM))[n];
    float4 o;
    o.x = tf32r( w4.x * qw + w4.y * qi + w4.z * qj + w4.w * qk);
    o.y = tf32r(-w4.x * qi + w4.y * qw + w4.z * qk - w4.w * qj);
    o.z = tf32r(-w4.x * qj - w4.y * qk + w4.z * qw + w4.w * qi);
    o.w = tf32r(-w4.x * qk + w4.y * qj - w4.z * qi + w4.w * qw);
    ((float4*)(g_weff + (size_t)a * STATE_DIM))[n] = o;
}

// ---------------- GEMM: out[65536,256] = X @ Weff^T + b ----------------
__device__ __forceinline__ void load_stage(float* smem, const float* __restrict__ x,
                                           int row0, int col0, int kt, int s, int tid,
                                           uint32_t sbase) {
    // A: BM x BK floats = 2048 float4 (4 per thread)
    float* sa = smem + s * A_STG_FLOATS;
    const float* xk = x + (size_t)row0 * STATE_DIM + kt * BK;
#pragma unroll
    for (int i = 0; i < 4; ++i) {
        int e = tid + i * THREADS;          // 0..2047
        int m = e >> 3, seg = e & 7;
        uint32_t dst = sbase + (uint32_t)((sa - smem) + m * PADK + seg * 4) * 4u;
        cp16(dst, xk + (size_t)m * STATE_DIM + seg * 4);
    }
    // B: BN x BK floats = 1024 float4 (2 per thread)
    float* sb = smem + 2 * A_STG_FLOATS + s * B_STG_FLOATS;
    const float* wk = g_weff + (size_t)col0 * STATE_DIM + kt * BK;
#pragma unroll
    for (int i = 0; i < 2; ++i) {
        int e = tid + i * THREADS;          // 0..1023
        int n = e >> 3, seg = e & 7;
        uint32_t dst = sbase + (uint32_t)((sb - smem) + n * PADK + seg * 4) * 4u;
        cp16(dst, wk + (size_t)n * STATE_DIM + seg * 4);
    }
}

__global__ void __launch_bounds__(THREADS, 1)
gemm_tf32(const float* __restrict__ x, const float* __restrict__ bias, float* __restrict__ out) {
    extern __shared__ float smem[];
    const uint32_t sbase = smem_u32(smem);
    const int tid = threadIdx.x;
    const int lane = tid & 31, warp = tid >> 5;
    const int wm = warp >> 2;          // 0..3  -> 64-row slice
    const int wn = warp & 3;           // 0..3  -> 32-col slice
    const int col0 = blockIdx.x * BN;  // x is fast dim: adjacent bids share the A tile in L2
    const int row0 = blockIdx.y * BM;

    float acc[4][4][4];
#pragma unroll
    for (int i = 0; i < 4; ++i)
#pragma unroll
        for (int j = 0; j < 4; ++j)
#pragma unroll
            for (int k = 0; k < 4; ++k) acc[i][j][k] = 0.f;

    // prologue: stages 0 and 1
    load_stage(smem, x, row0, col0, 0, 0, tid, sbase);
    asm volatile("cp.async.commit_group;" ::: "memory");
    load_stage(smem, x, row0, col0, 1, 1, tid, sbase);
    asm volatile("cp.async.commit_group;" ::: "memory");
    asm volatile("cp.async.wait_group 1;" ::: "memory");
    __syncthreads();

    const int rquad = lane >> 2;   // 0..7
    const int kq = lane & 3;       // 0..3

#pragma unroll 1
    for (int kt = 0; kt < NSTEPS; ++kt) {
        const int s = kt & 1;
        const float* sa = smem + s * A_STG_FLOATS;
        const float* sb = smem + 2 * A_STG_FLOATS + s * B_STG_FLOATS;

#pragma unroll
        for (int kk = 0; kk < 4; ++kk) {
            const int k0 = kk * 8 + kq;
            uint32_t af[4][4];
#pragma unroll
            for (int mt = 0; mt < 4; ++mt) {
                const int m = wm * 64 + mt * 16 + rquad;
                af[mt][0] = f2tf32(sa[m * PADK + k0]);
                af[mt][1] = f2tf32(sa[(m + 8) * PADK + k0]);
                af[mt][2] = f2tf32(sa[m * PADK + k0 + 4]);
                af[mt][3] = f2tf32(sa[(m + 8) * PADK + k0 + 4]);
            }
            uint32_t bf[4][2];
#pragma unroll
            for (int nt = 0; nt < 4; ++nt) {
                const int n = wn * 32 + nt * 8 + rquad;
                bf[nt][0] = f2tf32(sb[n * PADK + k0]);
                bf[nt][1] = f2tf32(sb[n * PADK + k0 + 4]);
            }
#pragma unroll
            for (int mt = 0; mt < 4; ++mt)
#pragma unroll
                for (int nt = 0; nt < 4; ++nt)
                    mma_tf32(acc[mt][nt], af[mt], bf[nt]);
        }

        __syncthreads();                       // everyone done reading stage s
        if (kt + 2 < NSTEPS)
            load_stage(smem, x, row0, col0, kt + 2, s, tid, sbase);
        asm volatile("cp.async.commit_group;" ::: "memory");
        asm volatile("cp.async.wait_group 1;" ::: "memory");   // stage kt+1 resident
        __syncthreads();
    }

    // epilogue: acc + bias -> out (fp32)
#pragma unroll
    for (int nt = 0; nt < 4; ++nt) {
        const int c = col0 + wn * 32 + nt * 8 + 2 * kq;
        const float b0 = __ldg(bias + c), b1 = __ldg(bias + c + 1);
#pragma unroll
        for (int mt = 0; mt < 4; ++mt) {
            const int r = row0 + wm * 64 + mt * 16 + rquad;
            float2 v0 = {acc[mt][nt][0] + b0, acc[mt][nt][1] + b1};
            float2 v1 = {acc[mt][nt][2] + b0, acc[mt][nt][3] + b1};
            *(float2*)(out + (size_t)r * NACT + c) = v0;
            *(float2*)(out + (size_t)(r + 8) * NACT + c) = v1;
        }
    }
}

// ---------------- launch ----------------
extern "C" void kernel_launch(void* const* d_in, const int* in_sizes, int n_in,
                              void* d_out, int out_size) {
    const float* x = (const float*)d_in[0];
    const float* g = (const float*)d_in[1];
    const float* W = (const float*)d_in[2];
    const float* b = (const float*)d_in[3];
    float* out = (float*)d_out;
    const int M = in_sizes[0] / STATE_DIM;     // 65536

    weff_kernel<<<NACT, 256>>>(W, g);

    cudaFuncSetAttribute(gemm_tf32, cudaFuncAttributeMaxDynamicSharedMemorySize, SMEM_BYTES);
    dim3 grid(NACT / BN, M / BM);              // (2, 256), x fast
    gemm_tf32<<<grid, THREADS, SMEM_BYTES>>>(x, b, out);
}

// round 6
// speedup vs baseline: 1.2561x; 1.2561x over previous
#include <cuda_runtime.h>
#include <cuda_fp16.h>
#include <cstdint>

#define STATE_DIM 1024
#define NACT 256
#define BM 256
#define BN 128
#define BK 32
#define NSTEPS (STATE_DIM / BK)    // 32
#define THREADS 512
#define PITCH 80                   // smem row pitch bytes (32 fp16 data + pad) -> conflict-free
#define A_STAGE (BM * PITCH)       // 20480
#define B_STAGE (BN * PITCH)       // 10240
#define STAGE (A_STAGE + B_STAGE)  // 30720
#define SMEM_BYTES (3 * STAGE)     // 92160

__device__ __half g_weffh[NACT * STATE_DIM];   // 512 KB static scratch (allowed)

// ---------------- helpers ----------------
__device__ __forceinline__ uint32_t smem_u32(const void* p) {
    uint32_t a;
    asm("{ .reg .u64 t; cvta.to.shared.u64 t, %1; cvt.u32.u64 %0, t; }" : "=r"(a) : "l"(p));
    return a;
}
__device__ __forceinline__ void cp16(uint32_t dst, const void* src) {
    asm volatile("cp.async.cg.shared.global [%0], [%1], 16;" :: "r"(dst), "l"(src) : "memory");
}
__device__ __forceinline__ uint32_t h2u(__half2 h) {
    return *reinterpret_cast<uint32_t*>(&h);
}
__device__ __forceinline__ void mma_f16(float* c, const uint32_t* a, const uint32_t* b) {
    asm volatile(
        "mma.sync.aligned.m16n8k16.row.col.f32.f16.f16.f32 "
        "{%0,%1,%2,%3}, {%4,%5,%6,%7}, {%8,%9}, {%0,%1,%2,%3};"
        : "+f"(c[0]), "+f"(c[1]), "+f"(c[2]), "+f"(c[3])
        : "r"(a[0]), "r"(a[1]), "r"(a[2]), "r"(a[3]), "r"(b[0]), "r"(b[1]));
}

// ---------------- W_eff precompute (fp32 math, fp16 output) ----------------
// Hamilton product is linear in x: h = M_n x_n with M_n from q = tanh(g).
// W_eff[a, 4n+d] = sum_c W[a,4n+c] * M_n[c,d], rounded to fp16 (rne).
__global__ void weff_kernel(const float* __restrict__ W, const float* __restrict__ g) {
    const int a = blockIdx.x;
    const int n = threadIdx.x;
    float4 q4 = ((const float4*)g)[n];
    float qw = tanhf(q4.x), qi = tanhf(q4.y), qj = tanhf(q4.z), qk = tanhf(q4.w);
    float4 w4 = ((const float4*)(W + (size_t)a * STATE_DIM))[n];
    float o0 =  w4.x * qw + w4.y * qi + w4.z * qj + w4.w * qk;
    float o1 = -w4.x * qi + w4.y * qw + w4.z * qk - w4.w * qj;
    float o2 = -w4.x * qj - w4.y * qk + w4.z * qw + w4.w * qi;
    float o3 = -w4.x * qk + w4.y * qj - w4.z * qi + w4.w * qw;
    __half2 h0 = __floats2half2_rn(o0, o1);
    __half2 h1 = __floats2half2_rn(o2, o3);
    uint2 u;
    u.x = h2u(h0);
    u.y = h2u(h1);
    *(uint2*)(g_weffh + (size_t)a * STATE_DIM + 4 * n) = u;
}

// ---------------- GEMM: out[65536,256] = X @ Weff^T + b (fp16 HMMA) ----------------
__device__ __forceinline__ void ldgA(float4 v[4], const float* __restrict__ x,
                                     int row0, int kt, int tid) {
    const int r = tid >> 1, hf = tid & 1;
    const float4* src = (const float4*)(x + (size_t)(row0 + r) * STATE_DIM + kt * BK + hf * 16);
    v[0] = src[0]; v[1] = src[1]; v[2] = src[2]; v[3] = src[3];
}
__device__ __forceinline__ void stsA(const float4 v[4], char* stage, int tid) {
    const int r = tid >> 1, hf = tid & 1;
    char* dst = stage + r * PITCH + hf * 32;
#pragma unroll
    for (int q = 0; q < 4; ++q) {
        uint2 u;
        u.x = h2u(__floats2half2_rn(v[q].x, v[q].y));   // low half = even k
        u.y = h2u(__floats2half2_rn(v[q].z, v[q].w));
        *(uint2*)(dst + q * 8) = u;
    }
}
__device__ __forceinline__ void cpB(uint32_t sbase, int s2, int col0, int kt, int tid) {
    const int n = tid >> 2, seg = tid & 3;
    const uint32_t dst = sbase + (uint32_t)s2 * STAGE + A_STAGE + n * PITCH + seg * 16;
    const __half* src = g_weffh + (size_t)(col0 + n) * STATE_DIM + kt * BK + seg * 8;
    cp16(dst, src);
}

__global__ void __launch_bounds__(THREADS, 1)
gemm_f16(const float* __restrict__ x, const float* __restrict__ bias, float* __restrict__ out) {
    extern __shared__ char smem[];
    const uint32_t sbase = smem_u32(smem);
    const int tid = threadIdx.x;
    const int lane = tid & 31, warp = tid >> 5;
    const int wm = warp >> 2;          // 0..3  -> 64-row slice
    const int wn = warp & 3;           // 0..3  -> 32-col slice
    const int gr = lane >> 2;          // groupID 0..7
    const int kq = lane & 3;           // threadID-in-group 0..3
    const int col0 = blockIdx.x * BN;  // x-fast: both N-blocks of a row share A in L2
    const int row0 = blockIdx.y * BM;

    float acc[4][4][4];
#pragma unroll
    for (int i = 0; i < 4; ++i)
#pragma unroll
        for (int j = 0; j < 4; ++j)
#pragma unroll
            for (int k = 0; k < 4; ++k) acc[i][j][k] = 0.f;

    // prologue: A stages 0,1 via reg-convert; B stages 0,1 via cp.async; A kt=2 in regs
    float4 v[4];
    ldgA(v, x, row0, 0, tid); stsA(v, smem + 0 * STAGE, tid);
    ldgA(v, x, row0, 1, tid); stsA(v, smem + 1 * STAGE, tid);
    cpB(sbase, 0, col0, 0, tid);
    asm volatile("cp.async.commit_group;" ::: "memory");
    cpB(sbase, 1, col0, 1, tid);
    asm volatile("cp.async.commit_group;" ::: "memory");
    ldgA(v, x, row0, 2, tid);
    asm volatile("cp.async.wait_group 1;" ::: "memory");   // B0 resident
    __syncthreads();

#pragma unroll 1
    for (int kt = 0; kt < NSTEPS; ++kt) {
        const int s = kt % 3;
        const int s2 = (kt + 2) % 3;   // free stage (readers of it finished before entry sync)

        if (kt + 2 < NSTEPS) {
            stsA(v, smem + s2 * STAGE, tid);
            cpB(sbase, s2, col0, kt + 2, tid);
        }
        asm volatile("cp.async.commit_group;" ::: "memory");   // may be empty near tail
        if (kt + 3 < NSTEPS)
            ldgA(v, x, row0, kt + 3, tid);

        const char* As = smem + s * STAGE;
        const char* Bs = As + A_STAGE;
#pragma unroll
        for (int kk = 0; kk < 2; ++kk) {               // two k16 chunks
            uint32_t af[4][4];
#pragma unroll
            for (int mt = 0; mt < 4; ++mt) {
                const char* p = As + (wm * 64 + mt * 16 + gr) * PITCH + kk * 32 + kq * 4;
                af[mt][0] = *(const uint32_t*)(p);
                af[mt][1] = *(const uint32_t*)(p + 8 * PITCH);
                af[mt][2] = *(const uint32_t*)(p + 16);
                af[mt][3] = *(const uint32_t*)(p + 8 * PITCH + 16);
            }
            uint32_t bf[4][2];
#pragma unroll
            for (int nt = 0; nt < 4; ++nt) {
                const char* p = Bs + (wn * 32 + nt * 8 + gr) * PITCH + kk * 32 + kq * 4;
                bf[nt][0] = *(const uint32_t*)(p);
                bf[nt][1] = *(const uint32_t*)(p + 16);
            }
#pragma unroll
            for (int mt = 0; mt < 4; ++mt)
#pragma unroll
                for (int nt = 0; nt < 4; ++nt)
                    mma_f16(acc[mt][nt], af[mt], bf[nt]);
        }

        asm volatile("cp.async.wait_group 1;" ::: "memory");   // B_{kt+1} resident
        __syncthreads();
    }

    // epilogue: acc + bias -> out (fp32)
#pragma unroll
    for (int nt = 0; nt < 4; ++nt) {
        const int c = col0 + wn * 32 + nt * 8 + 2 * kq;
        const float b0 = __ldg(bias + c), b1 = __ldg(bias + c + 1);
#pragma unroll
        for (int mt = 0; mt < 4; ++mt) {
            const int r = row0 + wm * 64 + mt * 16 + gr;
            float2 v0 = {acc[mt][nt][0] + b0, acc[mt][nt][1] + b1};
            float2 v1 = {acc[mt][nt][2] + b0, acc[mt][nt][3] + b1};
            *(float2*)(out + (size_t)r * NACT + c) = v0;
            *(float2*)(out + (size_t)(r + 8) * NACT + c) = v1;
        }
    }
}

// ---------------- launch ----------------
extern "C" void kernel_launch(void* const* d_in, const int* in_sizes, int n_in,
                              void* d_out, int out_size) {
    const float* x = (const float*)d_in[0];
    const float* g = (const float*)d_in[1];
    const float* W = (const float*)d_in[2];
    const float* b = (const float*)d_in[3];
    float* out = (float*)d_out;
    const int M = in_sizes[0] / STATE_DIM;     // 65536

    weff_kernel<<<NACT, 256>>>(W, g);

    cudaFuncSetAttribute(gemm_f16, cudaFuncAttributeMaxDynamicSharedMemorySize, SMEM_BYTES);
    dim3 grid(NACT / BN, M / BM);              // (2, 256), x fast
    gemm_f16<<<grid, THREADS, SMEM_BYTES>>>(x, b, out);
}